// round 1
// baseline (speedup 1.0000x reference)
#include <cuda_runtime.h>
#include <math.h>

#define Bb 128
#define Tt 1024
#define Ii 256
#define Hh 512
#define Vv 32000

// ---------------- scratch (static device globals; no allocations) ----------------
__device__ float g_Acat[Bb * 1280];        // [x | op | hp] per batch row
__device__ float g_Wcat[2048 * 1280];      // [W_ih row | W_hh row] per gate row
__device__ float g_bias[2048];             // b_ih + b_hh
__device__ float g_gates[Bb * 2048];
__device__ float g_q[Bb * Hh];
__device__ float g_scores[Bb * Tt];
__device__ float g_oin[Bb * 2 * Hh];       // [hn | context]

__device__ __forceinline__ float fast_tanh(float x) {
    float y;
    asm("tanh.approx.f32 %0, %1;" : "=f"(y) : "f"(x));
    return y;
}
__device__ __forceinline__ float sigmoidf(float x) {
    return 1.0f / (1.0f + expf(-x));
}

// ---------------- prep: build concatenated LSTM operands ----------------
__global__ void prep_cat(const float* __restrict__ x, const float* __restrict__ op,
                         const float* __restrict__ hp,
                         const float* __restrict__ Wih, const float* __restrict__ Whh,
                         const float* __restrict__ bih, const float* __restrict__ bhh) {
    int idx = blockIdx.x * blockDim.x + threadIdx.x;
    int stride = gridDim.x * blockDim.x;
    for (int i = idx; i < Bb * 1280; i += stride) {
        int b = i / 1280, k = i % 1280;
        float v;
        if (k < Ii)            v = x[b * Ii + k];
        else if (k < Ii + Hh)  v = op[b * Hh + (k - Ii)];
        else                   v = hp[b * Hh + (k - Ii - Hh)];
        g_Acat[i] = v;
    }
    for (int i = idx; i < 2048 * 1280; i += stride) {
        int j = i / 1280, k = i % 1280;
        g_Wcat[i] = (k < 768) ? Wih[j * 768 + k] : Whh[j * 512 + (k - 768)];
    }
    for (int i = idx; i < 2048; i += stride) g_bias[i] = bih[i] + bhh[i];
}

// ---------------- generic tiled GEMM: C[M,N] = A[M,K] @ B[N,K]^T ----------------
// BM=BN=64, BK=16, 256 threads, 4x4 per-thread tile.
// EPI: 0 = plain, 1 = +bias[n], 2 = tanhf
template <int EPI>
__global__ __launch_bounds__(256) void gemm64(const float* __restrict__ A,
                                              const float* __restrict__ Bm,
                                              const float* __restrict__ bias,
                                              float* __restrict__ C,
                                              int M, int N, int K) {
    __shared__ float As[16][68];
    __shared__ float Bs[16][68];
    int tid = threadIdx.x;
    int tx = tid & 15, ty = tid >> 4;
    int m0 = blockIdx.y * 64, n0 = blockIdx.x * 64;

    int lr = tid >> 2;          // 0..63
    int lc = (tid & 3) * 4;     // 0,4,8,12
    const float* Arow = A  + (size_t)(m0 + lr) * K + lc;
    const float* Brow = Bm + (size_t)(n0 + lr) * K + lc;

    float acc[4][4] = {};
    for (int k0 = 0; k0 < K; k0 += 16) {
        float4 av = *(const float4*)(Arow + k0);
        float4 bv = *(const float4*)(Brow + k0);
        As[lc + 0][lr] = av.x; As[lc + 1][lr] = av.y;
        As[lc + 2][lr] = av.z; As[lc + 3][lr] = av.w;
        Bs[lc + 0][lr] = bv.x; Bs[lc + 1][lr] = bv.y;
        Bs[lc + 2][lr] = bv.z; Bs[lc + 3][lr] = bv.w;
        __syncthreads();
#pragma unroll
        for (int k = 0; k < 16; k++) {
            float4 a = *(const float4*)&As[k][ty * 4];
            float4 b = *(const float4*)&Bs[k][tx * 4];
            acc[0][0] += a.x * b.x; acc[0][1] += a.x * b.y; acc[0][2] += a.x * b.z; acc[0][3] += a.x * b.w;
            acc[1][0] += a.y * b.x; acc[1][1] += a.y * b.y; acc[1][2] += a.y * b.z; acc[1][3] += a.y * b.w;
            acc[2][0] += a.z * b.x; acc[2][1] += a.z * b.y; acc[2][2] += a.z * b.z; acc[2][3] += a.z * b.w;
            acc[3][0] += a.w * b.x; acc[3][1] += a.w * b.y; acc[3][2] += a.w * b.z; acc[3][3] += a.w * b.w;
        }
        __syncthreads();
    }
#pragma unroll
    for (int i = 0; i < 4; i++) {
#pragma unroll
        for (int j = 0; j < 4; j++) {
            int m = m0 + ty * 4 + i;
            int n = n0 + tx * 4 + j;
            float v = acc[i][j];
            if (EPI == 1) v += bias[n];
            if (EPI == 2) v = tanhf(v);
            C[(size_t)m * N + n] = v;
        }
    }
}

// ---------------- LSTM pointwise ----------------
__global__ void lstm_pw(const float* __restrict__ cp,
                        float* __restrict__ out_hn, float* __restrict__ out_cn) {
    int i = blockIdx.x * blockDim.x + threadIdx.x;
    if (i >= Bb * Hh) return;
    int b = i / Hh, h = i % Hh;
    const float* g = g_gates + (size_t)b * 2048;
    float ig = sigmoidf(g[h]);
    float fg = sigmoidf(g[512 + h]);
    float gg = tanhf(g[1024 + h]);
    float og = sigmoidf(g[1536 + h]);
    float cn = fg * cp[i] + ig * gg;
    float hn = og * tanhf(cn);
    out_cn[i] = cn;
    out_hn[i] = hn;
    g_oin[(size_t)b * 1024 + h] = hn;   // first half of o_in
}

// ---------------- fused score kernel ----------------
// scores[b,t] = sum_n Wa[n] * tanh( q[b,n] + sum_k enc[b,t,k]*Wm[n,k] )
// CTA handles 64 consecutive (b,t) rows (tile never crosses b since 1024%64==0),
// loops the N=512 dimension in 8 chunks of 64, accumulating the Wa-weighted
// tanh reduction so the 268MB "k" tensor is never materialized.
__global__ __launch_bounds__(256) void score_kernel(const float* __restrict__ enc,
                                                    const float* __restrict__ Wm,
                                                    const float* __restrict__ Wa) {
    __shared__ float As[16][68];
    __shared__ float Bs[16][68];
    __shared__ float qs[512];
    __shared__ float was[512];
    __shared__ float rowacc[64];

    int tid = threadIdx.x;
    int tx = tid & 15, ty = tid >> 4;
    int r0 = blockIdx.x * 64;
    int b = r0 >> 10;

    for (int i = tid; i < 512; i += 256) {
        qs[i] = g_q[(size_t)b * 512 + i];
        was[i] = Wa[i];
    }
    if (tid < 64) rowacc[tid] = 0.0f;
    __syncthreads();

    int lr = tid >> 2;
    int lc = (tid & 3) * 4;
    const float* Arow = enc + (size_t)(r0 + lr) * 512 + lc;

    for (int n0 = 0; n0 < 512; n0 += 64) {
        float acc[4][4] = {};
        const float* Brow = Wm + (size_t)(n0 + lr) * 512 + lc;
        for (int k0 = 0; k0 < 512; k0 += 16) {
            float4 av = *(const float4*)(Arow + k0);
            float4 bv = *(const float4*)(Brow + k0);
            As[lc + 0][lr] = av.x; As[lc + 1][lr] = av.y;
            As[lc + 2][lr] = av.z; As[lc + 3][lr] = av.w;
            Bs[lc + 0][lr] = bv.x; Bs[lc + 1][lr] = bv.y;
            Bs[lc + 2][lr] = bv.z; Bs[lc + 3][lr] = bv.w;
            __syncthreads();
#pragma unroll
            for (int k = 0; k < 16; k++) {
                float4 a = *(const float4*)&As[k][ty * 4];
                float4 b4 = *(const float4*)&Bs[k][tx * 4];
                acc[0][0] += a.x * b4.x; acc[0][1] += a.x * b4.y; acc[0][2] += a.x * b4.z; acc[0][3] += a.x * b4.w;
                acc[1][0] += a.y * b4.x; acc[1][1] += a.y * b4.y; acc[1][2] += a.y * b4.z; acc[1][3] += a.y * b4.w;
                acc[2][0] += a.z * b4.x; acc[2][1] += a.z * b4.y; acc[2][2] += a.z * b4.z; acc[2][3] += a.z * b4.w;
                acc[3][0] += a.w * b4.x; acc[3][1] += a.w * b4.y; acc[3][2] += a.w * b4.z; acc[3][3] += a.w * b4.w;
            }
            __syncthreads();
        }
        // epilogue: tanh + Wa-weighted reduction over this 64-column chunk
        float part[4];
#pragma unroll
        for (int i = 0; i < 4; i++) {
            float s = 0.0f;
#pragma unroll
            for (int j = 0; j < 4; j++) {
                int n = n0 + tx * 4 + j;
                s += was[n] * fast_tanh(acc[i][j] + qs[n]);
            }
            part[i] = s;
        }
#pragma unroll
        for (int off = 8; off > 0; off >>= 1) {
#pragma unroll
            for (int i = 0; i < 4; i++)
                part[i] += __shfl_down_sync(0xffffffffu, part[i], off, 16);
        }
        if (tx == 0) {
#pragma unroll
            for (int i = 0; i < 4; i++) rowacc[ty * 4 + i] += part[i];
        }
        __syncthreads();
    }
    if (tid < 64) g_scores[r0 + tid] = rowacc[tid];
}

// ---------------- softmax over T + context ----------------
__global__ __launch_bounds__(256) void softmax_ctx(const float* __restrict__ enc,
                                                   float* __restrict__ out_w) {
    int b = blockIdx.x;
    int tid = threadIdx.x;
    __shared__ float w[1024];
    __shared__ float red[256];

    float lmax = -1e30f;
    for (int i = tid; i < 1024; i += 256) {
        float v = g_scores[(size_t)b * 1024 + i];
        w[i] = v;
        lmax = fmaxf(lmax, v);
    }
    red[tid] = lmax; __syncthreads();
    for (int s = 128; s > 0; s >>= 1) {
        if (tid < s) red[tid] = fmaxf(red[tid], red[tid + s]);
        __syncthreads();
    }
    float smax = red[0];
    __syncthreads();

    float lsum = 0.0f;
    for (int i = tid; i < 1024; i += 256) {
        float e = expf(w[i] - smax);
        w[i] = e;
        lsum += e;
    }
    red[tid] = lsum; __syncthreads();
    for (int s = 128; s > 0; s >>= 1) {
        if (tid < s) red[tid] += red[tid + s];
        __syncthreads();
    }
    float inv = 1.0f / red[0];
    __syncthreads();

    for (int i = tid; i < 1024; i += 256) {
        float wi = w[i] * inv;
        w[i] = wi;
        out_w[(size_t)b * 1024 + i] = wi;
    }
    __syncthreads();

    // context: 512 features, 2 per thread
    int h0 = tid, h1 = tid + 256;
    float c0 = 0.0f, c1 = 0.0f;
    const float* eb = enc + (size_t)b * 1024 * 512;
    for (int t = 0; t < 1024; t++) {
        float wt = w[t];
        const float* e = eb + (size_t)t * 512;
        c0 += wt * e[h0];
        c1 += wt * e[h1];
    }
    g_oin[(size_t)b * 1024 + 512 + h0] = c0;
    g_oin[(size_t)b * 1024 + 512 + h1] = c1;
}

// ---------------- log_softmax over V (in-place) ----------------
__global__ __launch_bounds__(256) void logsm(float* __restrict__ out) {
    int b = blockIdx.x;
    int tid = threadIdx.x;
    __shared__ float red[256];
    float* row = out + (size_t)b * Vv;

    float lmax = -1e30f;
    for (int i = tid; i < Vv; i += 256) lmax = fmaxf(lmax, row[i]);
    red[tid] = lmax; __syncthreads();
    for (int s = 128; s > 0; s >>= 1) {
        if (tid < s) red[tid] = fmaxf(red[tid], red[tid + s]);
        __syncthreads();
    }
    float m = red[0];
    __syncthreads();

    float lsum = 0.0f;
    for (int i = tid; i < Vv; i += 256) lsum += expf(row[i] - m);
    red[tid] = lsum; __syncthreads();
    for (int s = 128; s > 0; s >>= 1) {
        if (tid < s) red[tid] += red[tid + s];
        __syncthreads();
    }
    float lse = m + logf(red[0]);
    __syncthreads();

    for (int i = tid; i < Vv; i += 256) row[i] -= lse;
}

// ---------------- launch ----------------
extern "C" void kernel_launch(void* const* d_in, const int* in_sizes, int n_in,
                              void* d_out, int out_size) {
    const float* x    = (const float*)d_in[0];
    const float* hp   = (const float*)d_in[1];
    const float* cp   = (const float*)d_in[2];
    const float* op   = (const float*)d_in[3];
    const float* enc  = (const float*)d_in[4];
    const float* Wih  = (const float*)d_in[5];
    const float* Whh  = (const float*)d_in[6];
    const float* bih  = (const float*)d_in[7];
    const float* bhh  = (const float*)d_in[8];
    const float* Wq   = (const float*)d_in[9];
    const float* Wm   = (const float*)d_in[10];
    const float* Wa   = (const float*)d_in[11];
    const float* Wo   = (const float*)d_in[12];
    const float* Wout = (const float*)d_in[13];

    float* out        = (float*)d_out;
    float* out_logits = out;
    float* out_hn     = out + (size_t)Bb * Vv;
    float* out_cn     = out_hn + Bb * Hh;
    float* out_on     = out_cn + Bb * Hh;
    float* out_w      = out_on + Bb * Hh;

    float *pAcat, *pWcat, *pbias, *pgates, *pq, *poin;
    cudaGetSymbolAddress((void**)&pAcat,  g_Acat);
    cudaGetSymbolAddress((void**)&pWcat,  g_Wcat);
    cudaGetSymbolAddress((void**)&pbias,  g_bias);
    cudaGetSymbolAddress((void**)&pgates, g_gates);
    cudaGetSymbolAddress((void**)&pq,     g_q);
    cudaGetSymbolAddress((void**)&poin,   g_oin);

    // 1. concat LSTM operands
    prep_cat<<<256, 256>>>(x, op, hp, Wih, Whh, bih, bhh);
    // 2. gates = Acat @ Wcat^T + bias   (128 x 2048, K=1280)
    gemm64<1><<<dim3(32, 2), 256>>>(pAcat, pWcat, pbias, pgates, 128, 2048, 1280);
    // 3. LSTM pointwise -> hn, cn, o_in[:,:512]
    lstm_pw<<<256, 256>>>(cp, out_hn, out_cn);
    // 4. q = hn @ Wq^T  (128 x 512, K=512)
    gemm64<0><<<dim3(8, 2), 256>>>(out_hn, Wq, nullptr, pq, 128, 512, 512);
    // 5. fused scores = Wa . tanh(q + enc@Wm^T)   (131072 rows)
    score_kernel<<<2048, 256>>>(enc, Wm, Wa);
    // 6. softmax over T + context -> o_in[:,512:]
    softmax_ctx<<<128, 256>>>(enc, out_w);
    // 7. on = tanh(o_in @ Wo^T)  (128 x 512, K=1024)
    gemm64<2><<<dim3(8, 2), 256>>>(poin, Wo, nullptr, out_on, 128, 512, 1024);
    // 8. logits = on @ Wout^T  (128 x 32000, K=512)
    gemm64<0><<<dim3(500, 2), 256>>>(out_on, Wout, nullptr, out_logits, 128, 32000, 512);
    // 9. log_softmax in place
    logsm<<<128, 256>>>(out_logits);
}

// round 2
// speedup vs baseline: 1.9301x; 1.9301x over previous
#include <cuda_runtime.h>
#include <math.h>
#include <stdint.h>

#define Bb 128
#define Tt 1024
#define Ii 256
#define Hh 512
#define Vv 32000

// ---------------- scratch (static device globals; no allocations) ----------------
__device__ float g_Acat[Bb * 1280];        // [x | op | hp] per batch row
__device__ float g_Wcat[2048 * 1280];      // [W_ih row | W_hh row] per gate row
__device__ float g_bias[2048];             // b_ih + b_hh
__device__ float g_gates[Bb * 2048];
__device__ float g_q[Bb * Hh];
__device__ float g_scores[Bb * Tt];
__device__ float g_oin[Bb * 2 * Hh];       // [hn | context]

__device__ __forceinline__ float fast_tanh(float x) {
    float y;
    asm("tanh.approx.f32 %0, %1;" : "=f"(y) : "f"(x));
    return y;
}
__device__ __forceinline__ float sigmoidf(float x) {
    return 1.0f / (1.0f + expf(-x));
}
__device__ __forceinline__ unsigned f2tf(float x) {
    unsigned u;
    asm("cvt.rna.tf32.f32 %0, %1;" : "=r"(u) : "f"(x));
    return u;
}
__device__ __forceinline__ void mma8(float c[4], const unsigned a[4], const unsigned b[2]) {
    asm("mma.sync.aligned.m16n8k8.row.col.f32.tf32.tf32.f32 "
        "{%0,%1,%2,%3},{%4,%5,%6,%7},{%8,%9},{%0,%1,%2,%3};"
        : "+f"(c[0]), "+f"(c[1]), "+f"(c[2]), "+f"(c[3])
        : "r"(a[0]), "r"(a[1]), "r"(a[2]), "r"(a[3]), "r"(b[0]), "r"(b[1]));
}

// ---------------- prep: build concatenated LSTM operands ----------------
__global__ void prep_cat(const float* __restrict__ x, const float* __restrict__ op,
                         const float* __restrict__ hp,
                         const float* __restrict__ Wih, const float* __restrict__ Whh,
                         const float* __restrict__ bih, const float* __restrict__ bhh) {
    int idx = blockIdx.x * blockDim.x + threadIdx.x;
    int stride = gridDim.x * blockDim.x;
    for (int i = idx; i < Bb * 1280; i += stride) {
        int b = i / 1280, k = i % 1280;
        float v;
        if (k < Ii)            v = x[b * Ii + k];
        else if (k < Ii + Hh)  v = op[b * Hh + (k - Ii)];
        else                   v = hp[b * Hh + (k - Ii - Hh)];
        g_Acat[i] = v;
    }
    for (int i = idx; i < 2048 * 1280; i += stride) {
        int j = i / 1280, k = i % 1280;
        g_Wcat[i] = (k < 768) ? Wih[j * 768 + k] : Whh[j * 512 + (k - 768)];
    }
    for (int i = idx; i < 2048; i += stride) g_bias[i] = bih[i] + bhh[i];
}

// ---------------- tf32 MMA GEMM: C[M,N] = A[M,K] @ B[N,K]^T ----------------
// M must be 128. CTA tile 128x64, 8 warps (4 row x 2 col), warp tile 32x32.
// Smem tiles stored pre-permuted in fragment order:
//   A frag (mt,ks): 128 u32, thread lane holds [lane*4 .. lane*4+3] = one LDS.128
//   B frag (nt,ks): 64 u32,  thread lane holds [lane*2 .. lane*2+1] = one LDS.64
// EPI: 0 plain, 1 +bias[n], 2 tanh
template <int EPI>
__global__ __launch_bounds__(256) void mma_gemm(const float* __restrict__ A,
                                                const float* __restrict__ Bm,
                                                const float* __restrict__ bias,
                                                float* __restrict__ C,
                                                int N, int K) {
    __shared__ unsigned uA[8 * 4 * 128];   // 8 m-tiles x 4 k-steps
    __shared__ unsigned uB[8 * 4 * 64];    // 8 n-tiles x 4 k-steps
    int tid = threadIdx.x, lane = tid & 31, w = tid >> 5;
    int wr = w & 3, wc = w >> 2;
    int n0 = blockIdx.x * 64;
    int g = lane >> 2, t = lane & 3;

    float acc[2][4][4] = {};

    for (int k0 = 0; k0 < K; k0 += 32) {
        // fill A (128 rows x 32 k)
#pragma unroll
        for (int it = 0; it < 4; ++it) {
            int i = tid + it * 256;        // 0..1023
            int row = i >> 3, c = i & 7;
            int kk0 = c * 4;
            float4 v = *(const float4*)(A + (size_t)row * K + k0 + kk0);
            int mt = row >> 4, rr = row & 15;
            int gg = rr & 7, hi = rr >> 3;
            int ks = kk0 >> 3, half = (kk0 >> 2) & 1;
            unsigned* p = &uA[(mt * 4 + ks) * 128 + gg * 16 + half * 2 + hi];
            p[0] = f2tf(v.x); p[4] = f2tf(v.y); p[8] = f2tf(v.z); p[12] = f2tf(v.w);
        }
        // fill B (64 n x 32 k)
#pragma unroll
        for (int it = 0; it < 2; ++it) {
            int i = tid + it * 256;        // 0..511
            int n = i >> 3, c = i & 7;
            int kk0 = c * 4;
            float4 v = *(const float4*)(Bm + (size_t)(n0 + n) * K + k0 + kk0);
            int nt = n >> 3, gg = n & 7;
            int ks = kk0 >> 3, half = (kk0 >> 2) & 1;
            unsigned* p = &uB[(nt * 4 + ks) * 64 + gg * 8 + half];
            p[0] = f2tf(v.x); p[2] = f2tf(v.y); p[4] = f2tf(v.z); p[6] = f2tf(v.w);
        }
        __syncthreads();
#pragma unroll
        for (int ks = 0; ks < 4; ++ks) {
            unsigned a0[4], a1[4], b[4][2];
            *(uint4*)a0 = *(const uint4*)&uA[((wr * 2 + 0) * 4 + ks) * 128 + lane * 4];
            *(uint4*)a1 = *(const uint4*)&uA[((wr * 2 + 1) * 4 + ks) * 128 + lane * 4];
#pragma unroll
            for (int j = 0; j < 4; ++j)
                *(uint2*)b[j] = *(const uint2*)&uB[((wc * 4 + j) * 4 + ks) * 64 + lane * 2];
#pragma unroll
            for (int j = 0; j < 4; ++j) {
                mma8(acc[0][j], a0, b[j]);
                mma8(acc[1][j], a1, b[j]);
            }
        }
        __syncthreads();
    }
#pragma unroll
    for (int mt = 0; mt < 2; ++mt)
#pragma unroll
        for (int j = 0; j < 4; ++j)
#pragma unroll
            for (int ci = 0; ci < 4; ++ci) {
                int row = wr * 32 + mt * 16 + g + (ci >> 1) * 8;
                int col = n0 + wc * 32 + j * 8 + t * 2 + (ci & 1);
                float v = acc[mt][j][ci];
                if (EPI == 1) v += bias[col];
                if (EPI == 2) v = tanhf(v);
                C[(size_t)row * N + col] = v;
            }
}

// ---------------- fused score kernel (tf32 MMA) ----------------
// scores[b,t] = sum_n Wa[n]*tanh(q[b,n] + sum_k enc[b,t,k]*Wm[n,k])
// CTA: 64 rows of (b,t), loops n in 4 chunks of 128. 8 warps: 2 row x 4 col,
// warp tile 32x32. tanh+Wa reduction fused in epilogue (k tensor never stored).
__global__ __launch_bounds__(256) void score_kernel(const float* __restrict__ enc,
                                                    const float* __restrict__ Wm,
                                                    const float* __restrict__ Wa) {
    __shared__ unsigned uA[4 * 4 * 128];   // 4 m-tiles x 4 k-steps (64 rows)
    __shared__ unsigned uB[16 * 4 * 64];   // 16 n-tiles x 4 k-steps (128 n)
    __shared__ float qs[512];
    __shared__ float was[512];
    __shared__ float rowacc[64];

    int tid = threadIdx.x, lane = tid & 31, w = tid >> 5;
    int wr = w & 1, wc = w >> 1;           // 2 row-warps x 4 col-warps
    int r0 = blockIdx.x * 64;
    int b = r0 >> 10;
    int g = lane >> 2, t = lane & 3;

    for (int i = tid; i < 512; i += 256) {
        qs[i] = g_q[(size_t)b * 512 + i];
        was[i] = Wa[i];
    }
    if (tid < 64) rowacc[tid] = 0.0f;
    __syncthreads();

    for (int n0c = 0; n0c < 512; n0c += 128) {
        float acc[2][4][4] = {};
        for (int k0 = 0; k0 < 512; k0 += 32) {
            // fill A (64 rows x 32 k)
#pragma unroll
            for (int it = 0; it < 2; ++it) {
                int i = tid + it * 256;    // 0..511
                int row = i >> 3, c = i & 7;
                int kk0 = c * 4;
                float4 v = *(const float4*)(enc + (size_t)(r0 + row) * 512 + k0 + kk0);
                int mt = row >> 4, rr = row & 15;
                int gg = rr & 7, hi = rr >> 3;
                int ks = kk0 >> 3, half = (kk0 >> 2) & 1;
                unsigned* p = &uA[(mt * 4 + ks) * 128 + gg * 16 + half * 2 + hi];
                p[0] = f2tf(v.x); p[4] = f2tf(v.y); p[8] = f2tf(v.z); p[12] = f2tf(v.w);
            }
            // fill B (128 n x 32 k)
#pragma unroll
            for (int it = 0; it < 4; ++it) {
                int i = tid + it * 256;    // 0..1023
                int n = i >> 3, c = i & 7;
                int kk0 = c * 4;
                float4 v = *(const float4*)(Wm + (size_t)(n0c + n) * 512 + k0 + kk0);
                int nt = n >> 3, gg = n & 7;
                int ks = kk0 >> 3, half = (kk0 >> 2) & 1;
                unsigned* p = &uB[(nt * 4 + ks) * 64 + gg * 8 + half];
                p[0] = f2tf(v.x); p[2] = f2tf(v.y); p[4] = f2tf(v.z); p[6] = f2tf(v.w);
            }
            __syncthreads();
#pragma unroll
            for (int ks = 0; ks < 4; ++ks) {
                unsigned a0[4], a1[4], bf[4][2];
                *(uint4*)a0 = *(const uint4*)&uA[((wr * 2 + 0) * 4 + ks) * 128 + lane * 4];
                *(uint4*)a1 = *(const uint4*)&uA[((wr * 2 + 1) * 4 + ks) * 128 + lane * 4];
#pragma unroll
                for (int j = 0; j < 4; ++j)
                    *(uint2*)bf[j] = *(const uint2*)&uB[((wc * 4 + j) * 4 + ks) * 64 + lane * 2];
#pragma unroll
                for (int j = 0; j < 4; ++j) {
                    mma8(acc[0][j], a0, bf[j]);
                    mma8(acc[1][j], a1, bf[j]);
                }
            }
            __syncthreads();
        }
        // epilogue: tanh + Wa-weighted reduction over this 128-col chunk
        float p4[4] = {0.f, 0.f, 0.f, 0.f};
#pragma unroll
        for (int mt = 0; mt < 2; ++mt)
#pragma unroll
            for (int j = 0; j < 4; ++j)
#pragma unroll
                for (int ci = 0; ci < 4; ++ci) {
                    int n = n0c + wc * 32 + j * 8 + t * 2 + (ci & 1);
                    p4[mt * 2 + (ci >> 1)] += was[n] * fast_tanh(acc[mt][j][ci] + qs[n]);
                }
#pragma unroll
        for (int i = 0; i < 4; ++i) {
            p4[i] += __shfl_xor_sync(0xffffffffu, p4[i], 1);
            p4[i] += __shfl_xor_sync(0xffffffffu, p4[i], 2);
        }
        if (t == 0) {
#pragma unroll
            for (int i = 0; i < 4; ++i) {
                int mt = i >> 1, h = i & 1;
                int row = wr * 32 + mt * 16 + g + h * 8;
                atomicAdd(&rowacc[row], p4[i]);
            }
        }
    }
    __syncthreads();
    if (tid < 64) g_scores[r0 + tid] = rowacc[tid];
}

// ---------------- LSTM pointwise ----------------
__global__ void lstm_pw(const float* __restrict__ cp,
                        float* __restrict__ out_hn, float* __restrict__ out_cn) {
    int i = blockIdx.x * blockDim.x + threadIdx.x;
    if (i >= Bb * Hh) return;
    int b = i / Hh, h = i % Hh;
    const float* g = g_gates + (size_t)b * 2048;
    float ig = sigmoidf(g[h]);
    float fg = sigmoidf(g[512 + h]);
    float gg = tanhf(g[1024 + h]);
    float og = sigmoidf(g[1536 + h]);
    float cn = fg * cp[i] + ig * gg;
    float hn = og * tanhf(cn);
    out_cn[i] = cn;
    out_hn[i] = hn;
    g_oin[(size_t)b * 1024 + h] = hn;   // first half of o_in
}

// ---------------- softmax over T + context ----------------
__global__ __launch_bounds__(256) void softmax_ctx(const float* __restrict__ enc,
                                                   float* __restrict__ out_w) {
    int b = blockIdx.x;
    int tid = threadIdx.x;
    __shared__ float w[1024];
    __shared__ float red[256];

    float lmax = -1e30f;
    for (int i = tid; i < 1024; i += 256) {
        float v = g_scores[(size_t)b * 1024 + i];
        w[i] = v;
        lmax = fmaxf(lmax, v);
    }
    red[tid] = lmax; __syncthreads();
    for (int s = 128; s > 0; s >>= 1) {
        if (tid < s) red[tid] = fmaxf(red[tid], red[tid + s]);
        __syncthreads();
    }
    float smax = red[0];
    __syncthreads();

    float lsum = 0.0f;
    for (int i = tid; i < 1024; i += 256) {
        float e = expf(w[i] - smax);
        w[i] = e;
        lsum += e;
    }
    red[tid] = lsum; __syncthreads();
    for (int s = 128; s > 0; s >>= 1) {
        if (tid < s) red[tid] += red[tid + s];
        __syncthreads();
    }
    float inv = 1.0f / red[0];
    __syncthreads();

    for (int i = tid; i < 1024; i += 256) {
        float wi = w[i] * inv;
        w[i] = wi;
        out_w[(size_t)b * 1024 + i] = wi;
    }
    __syncthreads();

    // context: 512 features, 2 per thread
    int h0 = tid, h1 = tid + 256;
    float c0 = 0.0f, c1 = 0.0f;
    const float* eb = enc + (size_t)b * 1024 * 512;
    for (int tt = 0; tt < 1024; tt++) {
        float wt = w[tt];
        const float* e = eb + (size_t)tt * 512;
        c0 += wt * e[h0];
        c1 += wt * e[h1];
    }
    g_oin[(size_t)b * 1024 + 512 + h0] = c0;
    g_oin[(size_t)b * 1024 + 512 + h1] = c1;
}

// ---------------- log_softmax over V (in-place) ----------------
__global__ __launch_bounds__(256) void logsm(float* __restrict__ out) {
    int b = blockIdx.x;
    int tid = threadIdx.x;
    __shared__ float red[256];
    float* row = out + (size_t)b * Vv;

    float lmax = -1e30f;
    for (int i = tid; i < Vv; i += 256) lmax = fmaxf(lmax, row[i]);
    red[tid] = lmax; __syncthreads();
    for (int s = 128; s > 0; s >>= 1) {
        if (tid < s) red[tid] = fmaxf(red[tid], red[tid + s]);
        __syncthreads();
    }
    float m = red[0];
    __syncthreads();

    float lsum = 0.0f;
    for (int i = tid; i < Vv; i += 256) lsum += expf(row[i] - m);
    red[tid] = lsum; __syncthreads();
    for (int s = 128; s > 0; s >>= 1) {
        if (tid < s) red[tid] += red[tid + s];
        __syncthreads();
    }
    float lse = m + logf(red[0]);
    __syncthreads();

    for (int i = tid; i < Vv; i += 256) row[i] -= lse;
}

// ---------------- launch ----------------
extern "C" void kernel_launch(void* const* d_in, const int* in_sizes, int n_in,
                              void* d_out, int out_size) {
    const float* x    = (const float*)d_in[0];
    const float* hp   = (const float*)d_in[1];
    const float* cp   = (const float*)d_in[2];
    const float* op   = (const float*)d_in[3];
    const float* enc  = (const float*)d_in[4];
    const float* Wih  = (const float*)d_in[5];
    const float* Whh  = (const float*)d_in[6];
    const float* bih  = (const float*)d_in[7];
    const float* bhh  = (const float*)d_in[8];
    const float* Wq   = (const float*)d_in[9];
    const float* Wm   = (const float*)d_in[10];
    const float* Wa   = (const float*)d_in[11];
    const float* Wo   = (const float*)d_in[12];
    const float* Wout = (const float*)d_in[13];

    float* out        = (float*)d_out;
    float* out_logits = out;
    float* out_hn     = out + (size_t)Bb * Vv;
    float* out_cn     = out_hn + Bb * Hh;
    float* out_on     = out_cn + Bb * Hh;
    float* out_w      = out_on + Bb * Hh;

    float *pAcat, *pWcat, *pbias, *pgates, *pq, *poin;
    cudaGetSymbolAddress((void**)&pAcat,  g_Acat);
    cudaGetSymbolAddress((void**)&pWcat,  g_Wcat);
    cudaGetSymbolAddress((void**)&pbias,  g_bias);
    cudaGetSymbolAddress((void**)&pgates, g_gates);
    cudaGetSymbolAddress((void**)&pq,     g_q);
    cudaGetSymbolAddress((void**)&poin,   g_oin);

    // 1. concat LSTM operands
    prep_cat<<<256, 256>>>(x, op, hp, Wih, Whh, bih, bhh);
    // 2. gates = Acat @ Wcat^T + bias   (128 x 2048, K=1280)
    mma_gemm<1><<<32, 256>>>(pAcat, pWcat, pbias, pgates, 2048, 1280);
    // 3. LSTM pointwise -> hn, cn, o_in[:,:512]
    lstm_pw<<<256, 256>>>(cp, out_hn, out_cn);
    // 4. q = hn @ Wq^T  (128 x 512, K=512)
    mma_gemm<0><<<8, 256>>>(out_hn, Wq, nullptr, pq, 512, 512);
    // 5. fused scores = Wa . tanh(q + enc@Wm^T)   (131072 rows)
    score_kernel<<<2048, 256>>>(enc, Wm, Wa);
    // 6. softmax over T + context -> o_in[:,512:]
    softmax_ctx<<<128, 256>>>(enc, out_w);
    // 7. on = tanh(o_in @ Wo^T)  (128 x 512, K=1024)
    mma_gemm<2><<<8, 256>>>(poin, Wo, nullptr, out_on, 512, 1024);
    // 8. logits = on @ Wout^T  (128 x 32000, K=512)
    mma_gemm<0><<<500, 256>>>(out_on, Wout, nullptr, out_logits, 32000, 512);
    // 9. log_softmax in place
    logsm<<<128, 256>>>(out_logits);
}

// round 3
// speedup vs baseline: 2.0407x; 1.0573x over previous
#include <cuda_runtime.h>
#include <math.h>
#include <stdint.h>

#define Bb 128
#define Tt 1024
#define Ii 256
#define Hh 512
#define Vv 32000

// ---------------- scratch ----------------
__device__ float g_gates[Bb * 2048];
__device__ float g_q[Bb * Hh];
__device__ float g_scores[Bb * Tt];

__device__ __forceinline__ float fast_tanh(float x) {
    float y;
    asm("tanh.approx.f32 %0, %1;" : "=f"(y) : "f"(x));
    return y;
}
__device__ __forceinline__ float sigmoidf(float x) {
    return 1.0f / (1.0f + expf(-x));
}
__device__ __forceinline__ unsigned f2tf(float x) {
    unsigned u;
    asm("cvt.rna.tf32.f32 %0, %1;" : "=r"(u) : "f"(x));
    return u;
}
__device__ __forceinline__ void mma8(float c[4], const unsigned a[4], const unsigned b[2]) {
    asm("mma.sync.aligned.m16n8k8.row.col.f32.tf32.tf32.f32 "
        "{%0,%1,%2,%3},{%4,%5,%6,%7},{%8,%9},{%0,%1,%2,%3};"
        : "+f"(c[0]), "+f"(c[1]), "+f"(c[2]), "+f"(c[3])
        : "r"(a[0]), "r"(a[1]), "r"(a[2]), "r"(a[3]), "r"(b[0]), "r"(b[1]));
}

// frag-group strides (padded; keep 16B/8B alignment for LDS.128/LDS.64)
#define AS 132
#define BS 66

// ---------------- gates GEMM (concat-on-the-fly) ----------------
// gates[128,2048] = [x|op|hp] @ [Wih|Whh]^T + (bih+bhh).  K=1280.
__global__ __launch_bounds__(256) void gates_gemm(const float* __restrict__ x,
                                                  const float* __restrict__ op,
                                                  const float* __restrict__ hp,
                                                  const float* __restrict__ Wih,
                                                  const float* __restrict__ Whh,
                                                  const float* __restrict__ bih,
                                                  const float* __restrict__ bhh,
                                                  float* __restrict__ C) {
    __shared__ unsigned uA[32 * AS];
    __shared__ unsigned uB[32 * BS];
    int tid = threadIdx.x, lane = tid & 31, w = tid >> 5;
    int wr = w & 3, wc = w >> 2;
    int n0 = blockIdx.x * 64;
    int g = lane >> 2, t = lane & 3;

    float acc[2][4][4] = {};
    for (int k0 = 0; k0 < 1280; k0 += 32) {
#pragma unroll
        for (int it = 0; it < 4; ++it) {
            int i = tid + it * 256;
            int row = i >> 3, c = i & 7;
            int kk0 = c * 4, kk = k0 + kk0;
            float4 v;
            if (kk < 256)      v = *(const float4*)(x  + (size_t)row * 256 + kk);
            else if (kk < 768) v = *(const float4*)(op + (size_t)row * 512 + kk - 256);
            else               v = *(const float4*)(hp + (size_t)row * 512 + kk - 768);
            int mt = row >> 4, rr = row & 15, gg = rr & 7, hi = rr >> 3;
            int ks = kk0 >> 3, half = (kk0 >> 2) & 1;
            unsigned* p = &uA[(mt * 4 + ks) * AS + gg * 16 + half * 2 + hi];
            p[0] = f2tf(v.x); p[4] = f2tf(v.y); p[8] = f2tf(v.z); p[12] = f2tf(v.w);
        }
#pragma unroll
        for (int it = 0; it < 2; ++it) {
            int i = tid + it * 256;
            int n = i >> 3, c = i & 7;
            int kk0 = c * 4, kk = k0 + kk0;
            int j = n0 + n;
            float4 v = (kk < 768) ? *(const float4*)(Wih + (size_t)j * 768 + kk)
                                  : *(const float4*)(Whh + (size_t)j * 512 + kk - 768);
            int nt = n >> 3, gg = n & 7;
            int ks = kk0 >> 3, half = (kk0 >> 2) & 1;
            unsigned* p = &uB[(nt * 4 + ks) * BS + gg * 8 + half];
            p[0] = f2tf(v.x); p[2] = f2tf(v.y); p[4] = f2tf(v.z); p[6] = f2tf(v.w);
        }
        __syncthreads();
#pragma unroll
        for (int ks = 0; ks < 4; ++ks) {
            unsigned a0[4], a1[4], b[4][2];
            *(uint4*)a0 = *(const uint4*)&uA[((wr * 2 + 0) * 4 + ks) * AS + lane * 4];
            *(uint4*)a1 = *(const uint4*)&uA[((wr * 2 + 1) * 4 + ks) * AS + lane * 4];
#pragma unroll
            for (int j = 0; j < 4; ++j)
                *(uint2*)b[j] = *(const uint2*)&uB[((wc * 4 + j) * 4 + ks) * BS + lane * 2];
#pragma unroll
            for (int j = 0; j < 4; ++j) { mma8(acc[0][j], a0, b[j]); mma8(acc[1][j], a1, b[j]); }
        }
        __syncthreads();
    }
#pragma unroll
    for (int mt = 0; mt < 2; ++mt)
#pragma unroll
        for (int j = 0; j < 4; ++j)
#pragma unroll
            for (int ci = 0; ci < 4; ++ci) {
                int row = wr * 32 + mt * 16 + g + (ci >> 1) * 8;
                int col = n0 + wc * 32 + j * 8 + t * 2 + (ci & 1);
                C[(size_t)row * 2048 + col] = acc[mt][j][ci] + bih[col] + bhh[col];
            }
}

// ---------------- generic tf32 GEMM (used for logits) ----------------
template <int EPI>
__global__ __launch_bounds__(256) void mma_gemm(const float* __restrict__ A,
                                                const float* __restrict__ Bm,
                                                float* __restrict__ C,
                                                int N, int K) {
    __shared__ unsigned uA[32 * AS];
    __shared__ unsigned uB[32 * BS];
    int tid = threadIdx.x, lane = tid & 31, w = tid >> 5;
    int wr = w & 3, wc = w >> 2;
    int n0 = blockIdx.x * 64;
    int g = lane >> 2, t = lane & 3;

    float acc[2][4][4] = {};
    for (int k0 = 0; k0 < K; k0 += 32) {
#pragma unroll
        for (int it = 0; it < 4; ++it) {
            int i = tid + it * 256;
            int row = i >> 3, c = i & 7;
            int kk0 = c * 4;
            float4 v = *(const float4*)(A + (size_t)row * K + k0 + kk0);
            int mt = row >> 4, rr = row & 15, gg = rr & 7, hi = rr >> 3;
            int ks = kk0 >> 3, half = (kk0 >> 2) & 1;
            unsigned* p = &uA[(mt * 4 + ks) * AS + gg * 16 + half * 2 + hi];
            p[0] = f2tf(v.x); p[4] = f2tf(v.y); p[8] = f2tf(v.z); p[12] = f2tf(v.w);
        }
#pragma unroll
        for (int it = 0; it < 2; ++it) {
            int i = tid + it * 256;
            int n = i >> 3, c = i & 7;
            int kk0 = c * 4;
            float4 v = *(const float4*)(Bm + (size_t)(n0 + n) * K + k0 + kk0);
            int nt = n >> 3, gg = n & 7;
            int ks = kk0 >> 3, half = (kk0 >> 2) & 1;
            unsigned* p = &uB[(nt * 4 + ks) * BS + gg * 8 + half];
            p[0] = f2tf(v.x); p[2] = f2tf(v.y); p[4] = f2tf(v.z); p[6] = f2tf(v.w);
        }
        __syncthreads();
#pragma unroll
        for (int ks = 0; ks < 4; ++ks) {
            unsigned a0[4], a1[4], b[4][2];
            *(uint4*)a0 = *(const uint4*)&uA[((wr * 2 + 0) * 4 + ks) * AS + lane * 4];
            *(uint4*)a1 = *(const uint4*)&uA[((wr * 2 + 1) * 4 + ks) * AS + lane * 4];
#pragma unroll
            for (int j = 0; j < 4; ++j)
                *(uint2*)b[j] = *(const uint2*)&uB[((wc * 4 + j) * 4 + ks) * BS + lane * 2];
#pragma unroll
            for (int j = 0; j < 4; ++j) { mma8(acc[0][j], a0, b[j]); mma8(acc[1][j], a1, b[j]); }
        }
        __syncthreads();
    }
#pragma unroll
    for (int mt = 0; mt < 2; ++mt)
#pragma unroll
        for (int j = 0; j < 4; ++j)
#pragma unroll
            for (int ci = 0; ci < 4; ++ci) {
                int row = wr * 32 + mt * 16 + g + (ci >> 1) * 8;
                int col = n0 + wc * 32 + j * 8 + t * 2 + (ci & 1);
                float v = acc[mt][j][ci];
                if (EPI == 2) v = tanhf(v);
                C[(size_t)row * N + col] = v;
            }
}

// ---------------- fused LSTM pointwise + q = hn @ Wq^T ----------------
__global__ __launch_bounds__(256) void lstm_q(const float* __restrict__ cp,
                                              const float* __restrict__ Wq,
                                              float* __restrict__ out_hn,
                                              float* __restrict__ out_cn) {
    int b = blockIdx.x, tid = threadIdx.x;
    __shared__ float hns[512];
    const float* g = g_gates + (size_t)b * 2048;
#pragma unroll
    for (int h = tid; h < 512; h += 256) {
        float ig = sigmoidf(g[h]);
        float fg = sigmoidf(g[512 + h]);
        float gg = tanhf(g[1024 + h]);
        float og = sigmoidf(g[1536 + h]);
        float cn = fg * cp[(size_t)b * 512 + h] + ig * gg;
        float hn = og * tanhf(cn);
        out_cn[(size_t)b * 512 + h] = cn;
        out_hn[(size_t)b * 512 + h] = hn;
        hns[h] = hn;
    }
    __syncthreads();
#pragma unroll
    for (int n = tid; n < 512; n += 256) {
        const float4* wr = (const float4*)(Wq + (size_t)n * 512);
        float s = 0.0f;
#pragma unroll 4
        for (int i = 0; i < 128; ++i) {
            float4 v = wr[i];
            s += v.x * hns[i * 4] + v.y * hns[i * 4 + 1] + v.z * hns[i * 4 + 2] + v.w * hns[i * 4 + 3];
        }
        g_q[(size_t)b * 512 + n] = s;
    }
}

// ---------------- fused score kernel v2 ----------------
// A (enc, 64 rows x 512 k) resident in smem as tf32; B (Wm) double-buffered,
// register-pipelined. scores[b,t] = sum_n Wa[n]*tanh(q[b,n] + (enc@Wm^T)[t,n]).
#define SC_A_U32 (4 * 64 * AS)      /* 4 m-tiles x 64 ks */
#define SC_B_U32 (16 * 4 * BS)      /* 16 nt x 4 ks per 32-k chunk */
__global__ __launch_bounds__(256) void score_kernel(const float* __restrict__ enc,
                                                    const float* __restrict__ Wm,
                                                    const float* __restrict__ Wa) {
    extern __shared__ unsigned sm[];
    unsigned* uA  = sm;                       // SC_A_U32
    unsigned* uB0 = uA + SC_A_U32;            // SC_B_U32
    unsigned* uB1 = uB0 + SC_B_U32;           // SC_B_U32
    float* qs     = (float*)(uB1 + SC_B_U32); // 512
    float* was    = qs + 512;                 // 512
    float* rowacc = was + 512;                // 64

    int tid = threadIdx.x, lane = tid & 31, w = tid >> 5;
    int wr = w & 1, wc = w >> 1;              // 2 row-warps x 4 col-warps
    int r0 = blockIdx.x * 64;
    int b = r0 >> 10;
    int g = lane >> 2, t = lane & 3;

    for (int i = tid; i < 512; i += 256) {
        qs[i] = g_q[(size_t)b * 512 + i];
        was[i] = Wa[i];
    }
    if (tid < 64) rowacc[tid] = 0.0f;

    // ---- fill A once: 64 rows x 512 k ----
#pragma unroll
    for (int it = 0; it < 32; ++it) {
        int i = tid + it * 256;               // 0..8191 float4
        int row = i >> 7, c = i & 127;        // 128 float4 per row
        int kk0 = c * 4;
        float4 v = *(const float4*)(enc + (size_t)(r0 + row) * 512 + kk0);
        int mt = row >> 4, rr = row & 15, gg = rr & 7, hi = rr >> 3;
        int ks = kk0 >> 3, half = (kk0 >> 2) & 1;
        unsigned* p = &uA[(mt * 64 + ks) * AS + gg * 16 + half * 2 + hi];
        p[0] = f2tf(v.x); p[4] = f2tf(v.y); p[8] = f2tf(v.z); p[12] = f2tf(v.w);
    }
    __syncthreads();

    for (int n0c = 0; n0c < 512; n0c += 128) {
        float acc[2][4][4] = {};
        float4 vb[4];
        // prologue: load+store chunk 0
#pragma unroll
        for (int it = 0; it < 4; ++it) {
            int i = tid + it * 256;
            int n = i >> 3, c = i & 7;
            vb[it] = *(const float4*)(Wm + (size_t)(n0c + n) * 512 + c * 4);
        }
#pragma unroll
        for (int it = 0; it < 4; ++it) {
            int i = tid + it * 256;
            int n = i >> 3, c = i & 7;
            int kk0 = c * 4, nt = n >> 3, gg = n & 7;
            int ks = kk0 >> 3, half = (kk0 >> 2) & 1;
            unsigned* p = &uB0[(nt * 4 + ks) * BS + gg * 8 + half];
            p[0] = f2tf(vb[it].x); p[2] = f2tf(vb[it].y); p[4] = f2tf(vb[it].z); p[6] = f2tf(vb[it].w);
        }
        __syncthreads();

        for (int kc = 0; kc < 16; ++kc) {
            unsigned* cur = (kc & 1) ? uB1 : uB0;
            unsigned* nxt = (kc & 1) ? uB0 : uB1;
            if (kc < 15) {
#pragma unroll
                for (int it = 0; it < 4; ++it) {
                    int i = tid + it * 256;
                    int n = i >> 3, c = i & 7;
                    vb[it] = *(const float4*)(Wm + (size_t)(n0c + n) * 512 + (kc + 1) * 32 + c * 4);
                }
            }
#pragma unroll
            for (int ks = 0; ks < 4; ++ks) {
                int ksg = kc * 4 + ks;
                unsigned a0[4], a1[4], bf[4][2];
                *(uint4*)a0 = *(const uint4*)&uA[((wr * 2 + 0) * 64 + ksg) * AS + lane * 4];
                *(uint4*)a1 = *(const uint4*)&uA[((wr * 2 + 1) * 64 + ksg) * AS + lane * 4];
#pragma unroll
                for (int j = 0; j < 4; ++j)
                    *(uint2*)bf[j] = *(const uint2*)&cur[((wc * 4 + j) * 4 + ks) * BS + lane * 2];
#pragma unroll
                for (int j = 0; j < 4; ++j) { mma8(acc[0][j], a0, bf[j]); mma8(acc[1][j], a1, bf[j]); }
            }
            if (kc < 15) {
#pragma unroll
                for (int it = 0; it < 4; ++it) {
                    int i = tid + it * 256;
                    int n = i >> 3, c = i & 7;
                    int kk0 = c * 4, nt = n >> 3, gg = n & 7;
                    int ks = kk0 >> 3, half = (kk0 >> 2) & 1;
                    unsigned* p = &nxt[(nt * 4 + ks) * BS + gg * 8 + half];
                    p[0] = f2tf(vb[it].x); p[2] = f2tf(vb[it].y); p[4] = f2tf(vb[it].z); p[6] = f2tf(vb[it].w);
                }
            }
            __syncthreads();
        }

        // epilogue: tanh + Wa-weighted reduce over this 128-col chunk
        float p4[4] = {0.f, 0.f, 0.f, 0.f};
#pragma unroll
        for (int mt = 0; mt < 2; ++mt)
#pragma unroll
            for (int j = 0; j < 4; ++j)
#pragma unroll
                for (int ci = 0; ci < 4; ++ci) {
                    int n = n0c + wc * 32 + j * 8 + t * 2 + (ci & 1);
                    p4[mt * 2 + (ci >> 1)] += was[n] * fast_tanh(acc[mt][j][ci] + qs[n]);
                }
#pragma unroll
        for (int i = 0; i < 4; ++i) {
            p4[i] += __shfl_xor_sync(0xffffffffu, p4[i], 1);
            p4[i] += __shfl_xor_sync(0xffffffffu, p4[i], 2);
        }
        if (t == 0) {
#pragma unroll
            for (int i = 0; i < 4; ++i) {
                int mt = i >> 1, h = i & 1;
                atomicAdd(&rowacc[wr * 32 + mt * 16 + g + h * 8], p4[i]);
            }
        }
    }
    __syncthreads();
    if (tid < 64) g_scores[r0 + tid] = rowacc[tid];
}

// ---------------- softmax over T + context + Wo head ----------------
__global__ __launch_bounds__(256) void softmax_ctx_wo(const float* __restrict__ enc,
                                                      const float* __restrict__ hn,
                                                      const float* __restrict__ Wo,
                                                      float* __restrict__ out_w,
                                                      float* __restrict__ out_on) {
    int b = blockIdx.x, tid = threadIdx.x;
    __shared__ float wbuf[1024];
    __shared__ float oin[1024];
    __shared__ float red[256];

    float lmax = -1e30f;
    for (int i = tid; i < 1024; i += 256) {
        float v = g_scores[(size_t)b * 1024 + i];
        wbuf[i] = v;
        lmax = fmaxf(lmax, v);
    }
    for (int i = tid; i < 512; i += 256) oin[i] = hn[(size_t)b * 512 + i];
    red[tid] = lmax; __syncthreads();
    for (int s = 128; s > 0; s >>= 1) {
        if (tid < s) red[tid] = fmaxf(red[tid], red[tid + s]);
        __syncthreads();
    }
    float smax = red[0];
    __syncthreads();

    float lsum = 0.0f;
    for (int i = tid; i < 1024; i += 256) {
        float e = expf(wbuf[i] - smax);
        wbuf[i] = e;
        lsum += e;
    }
    red[tid] = lsum; __syncthreads();
    for (int s = 128; s > 0; s >>= 1) {
        if (tid < s) red[tid] += red[tid + s];
        __syncthreads();
    }
    float inv = 1.0f / red[0];
    __syncthreads();

    for (int i = tid; i < 1024; i += 256) {
        float wi = wbuf[i] * inv;
        wbuf[i] = wi;
        out_w[(size_t)b * 1024 + i] = wi;
    }
    __syncthreads();

    // context
    int h0 = tid, h1 = tid + 256;
    float c0 = 0.0f, c1 = 0.0f;
    const float* eb = enc + (size_t)b * 1024 * 512;
#pragma unroll 4
    for (int tt = 0; tt < 1024; tt++) {
        float wt = wbuf[tt];
        const float* e = eb + (size_t)tt * 512;
        c0 += wt * e[h0];
        c1 += wt * e[h1];
    }
    oin[512 + h0] = c0;
    oin[512 + h1] = c1;
    __syncthreads();

    // on = tanh(o_in @ Wo^T)
#pragma unroll
    for (int n = tid; n < 512; n += 256) {
        const float4* wr = (const float4*)(Wo + (size_t)n * 1024);
        float s = 0.0f;
#pragma unroll 4
        for (int i = 0; i < 256; ++i) {
            float4 v = wr[i];
            s += v.x * oin[i * 4] + v.y * oin[i * 4 + 1] + v.z * oin[i * 4 + 2] + v.w * oin[i * 4 + 3];
        }
        out_on[(size_t)b * 512 + n] = tanhf(s);
    }
}

// ---------------- log_softmax over V ----------------
__global__ __launch_bounds__(256) void logsm(float* __restrict__ out) {
    int b = blockIdx.x, tid = threadIdx.x;
    __shared__ float red[256];
    float* row = out + (size_t)b * Vv;

    float lmax = -1e30f;
    for (int i = tid; i < Vv; i += 256) lmax = fmaxf(lmax, row[i]);
    red[tid] = lmax; __syncthreads();
    for (int s = 128; s > 0; s >>= 1) {
        if (tid < s) red[tid] = fmaxf(red[tid], red[tid + s]);
        __syncthreads();
    }
    float m = red[0];
    __syncthreads();

    float lsum = 0.0f;
    for (int i = tid; i < Vv; i += 256) lsum += expf(row[i] - m);
    red[tid] = lsum; __syncthreads();
    for (int s = 128; s > 0; s >>= 1) {
        if (tid < s) red[tid] += red[tid + s];
        __syncthreads();
    }
    float lse = m + logf(red[0]);
    __syncthreads();

    for (int i = tid; i < Vv; i += 256) row[i] -= lse;
}

// ---------------- launch ----------------
extern "C" void kernel_launch(void* const* d_in, const int* in_sizes, int n_in,
                              void* d_out, int out_size) {
    const float* x    = (const float*)d_in[0];
    const float* hp   = (const float*)d_in[1];
    const float* cp   = (const float*)d_in[2];
    const float* op   = (const float*)d_in[3];
    const float* enc  = (const float*)d_in[4];
    const float* Wih  = (const float*)d_in[5];
    const float* Whh  = (const float*)d_in[6];
    const float* bih  = (const float*)d_in[7];
    const float* bhh  = (const float*)d_in[8];
    const float* Wq   = (const float*)d_in[9];
    const float* Wm   = (const float*)d_in[10];
    const float* Wa   = (const float*)d_in[11];
    const float* Wo   = (const float*)d_in[12];
    const float* Wout = (const float*)d_in[13];

    float* out        = (float*)d_out;
    float* out_logits = out;
    float* out_hn     = out + (size_t)Bb * Vv;
    float* out_cn     = out_hn + Bb * Hh;
    float* out_on     = out_cn + Bb * Hh;
    float* out_w      = out_on + Bb * Hh;

    float* pgates;
    cudaGetSymbolAddress((void**)&pgates, g_gates);

    size_t score_smem = (size_t)(SC_A_U32 + 2 * SC_B_U32 + 512 + 512 + 64) * 4;
    cudaFuncSetAttribute(score_kernel, cudaFuncAttributeMaxDynamicSharedMemorySize,
                         (int)score_smem);

    // 1. gates = [x|op|hp] @ [Wih|Whh]^T + bias
    gates_gemm<<<32, 256>>>(x, op, hp, Wih, Whh, bih, bhh, pgates);
    // 2. LSTM pointwise + q = hn @ Wq^T
    lstm_q<<<128, 256>>>(cp, Wq, out_hn, out_cn);
    // 3. fused scores
    score_kernel<<<2048, 256, score_smem>>>(enc, Wm, Wa);
    // 4. softmax + context + on = tanh(o_in @ Wo^T)
    softmax_ctx_wo<<<128, 256>>>(enc, out_hn, Wo, out_w, out_on);
    // 5. logits = on @ Wout^T
    mma_gemm<0><<<500, 256>>>(out_on, Wout, out_logits, 32000, 512);
    // 6. log_softmax in place
    logsm<<<128, 256>>>(out_logits);
}

// round 4
// speedup vs baseline: 2.4145x; 1.1832x over previous
#include <cuda_runtime.h>
#include <math.h>
#include <stdint.h>

#define Bb 128
#define Tt 1024
#define Ii 256
#define Hh 512
#define Vv 32000

// ---------------- scratch ----------------
__device__ float g_gates[Bb * 2048];
__device__ float g_q[Bb * Hh];
__device__ float g_scores[Bb * Tt];
__device__ float g_oin[Bb * 2 * Hh];   // [hn | context]

__device__ __forceinline__ float fast_tanh(float x) {
    float y;
    asm("tanh.approx.f32 %0, %1;" : "=f"(y) : "f"(x));
    return y;
}
__device__ __forceinline__ float sigmoidf(float x) {
    return 1.0f / (1.0f + expf(-x));
}
__device__ __forceinline__ unsigned f2tf(float x) {
    unsigned u;
    asm("cvt.rna.tf32.f32 %0, %1;" : "=r"(u) : "f"(x));
    return u;
}
__device__ __forceinline__ void mma8(float c[4], const unsigned a[4], const unsigned b[2]) {
    asm("mma.sync.aligned.m16n8k8.row.col.f32.tf32.tf32.f32 "
        "{%0,%1,%2,%3},{%4,%5,%6,%7},{%8,%9},{%0,%1,%2,%3};"
        : "+f"(c[0]), "+f"(c[1]), "+f"(c[2]), "+f"(c[3])
        : "r"(a[0]), "r"(a[1]), "r"(a[2]), "r"(a[3]), "r"(b[0]), "r"(b[1]));
}

#define AS 132
#define BS 66

// ---------------- gates GEMM (concat-on-the-fly) ----------------
__global__ __launch_bounds__(256) void gates_gemm(const float* __restrict__ x,
                                                  const float* __restrict__ op,
                                                  const float* __restrict__ hp,
                                                  const float* __restrict__ Wih,
                                                  const float* __restrict__ Whh,
                                                  const float* __restrict__ bih,
                                                  const float* __restrict__ bhh,
                                                  float* __restrict__ C) {
    __shared__ unsigned uA[32 * AS];
    __shared__ unsigned uB[32 * BS];
    int tid = threadIdx.x, lane = tid & 31, w = tid >> 5;
    int wr = w & 3, wc = w >> 2;
    int n0 = blockIdx.x * 64;
    int g = lane >> 2, t = lane & 3;

    float acc[2][4][4] = {};
    for (int k0 = 0; k0 < 1280; k0 += 32) {
#pragma unroll
        for (int it = 0; it < 4; ++it) {
            int i = tid + it * 256;
            int row = i >> 3, c = i & 7;
            int kk0 = c * 4, kk = k0 + kk0;
            float4 v;
            if (kk < 256)      v = *(const float4*)(x  + (size_t)row * 256 + kk);
            else if (kk < 768) v = *(const float4*)(op + (size_t)row * 512 + kk - 256);
            else               v = *(const float4*)(hp + (size_t)row * 512 + kk - 768);
            int mt = row >> 4, rr = row & 15, gg = rr & 7, hi = rr >> 3;
            int ks = kk0 >> 3, half = (kk0 >> 2) & 1;
            unsigned* p = &uA[(mt * 4 + ks) * AS + gg * 16 + half * 2 + hi];
            p[0] = f2tf(v.x); p[4] = f2tf(v.y); p[8] = f2tf(v.z); p[12] = f2tf(v.w);
        }
#pragma unroll
        for (int it = 0; it < 2; ++it) {
            int i = tid + it * 256;
            int n = i >> 3, c = i & 7;
            int kk0 = c * 4, kk = k0 + kk0;
            int j = n0 + n;
            float4 v = (kk < 768) ? *(const float4*)(Wih + (size_t)j * 768 + kk)
                                  : *(const float4*)(Whh + (size_t)j * 512 + kk - 768);
            int nt = n >> 3, gg = n & 7;
            int ks = kk0 >> 3, half = (kk0 >> 2) & 1;
            unsigned* p = &uB[(nt * 4 + ks) * BS + gg * 8 + half];
            p[0] = f2tf(v.x); p[2] = f2tf(v.y); p[4] = f2tf(v.z); p[6] = f2tf(v.w);
        }
        __syncthreads();
#pragma unroll
        for (int ks = 0; ks < 4; ++ks) {
            unsigned a0[4], a1[4], b[4][2];
            *(uint4*)a0 = *(const uint4*)&uA[((wr * 2 + 0) * 4 + ks) * AS + lane * 4];
            *(uint4*)a1 = *(const uint4*)&uA[((wr * 2 + 1) * 4 + ks) * AS + lane * 4];
#pragma unroll
            for (int j = 0; j < 4; ++j)
                *(uint2*)b[j] = *(const uint2*)&uB[((wc * 4 + j) * 4 + ks) * BS + lane * 2];
#pragma unroll
            for (int j = 0; j < 4; ++j) { mma8(acc[0][j], a0, b[j]); mma8(acc[1][j], a1, b[j]); }
        }
        __syncthreads();
    }
#pragma unroll
    for (int mt = 0; mt < 2; ++mt)
#pragma unroll
        for (int j = 0; j < 4; ++j)
#pragma unroll
            for (int ci = 0; ci < 4; ++ci) {
                int row = wr * 32 + mt * 16 + g + (ci >> 1) * 8;
                int col = n0 + wc * 32 + j * 8 + t * 2 + (ci & 1);
                C[(size_t)row * 2048 + col] = acc[mt][j][ci] + bih[col] + bhh[col];
            }
}

// ---------------- generic tf32 GEMM ----------------
template <int EPI>
__global__ __launch_bounds__(256) void mma_gemm(const float* __restrict__ A,
                                                const float* __restrict__ Bm,
                                                float* __restrict__ C,
                                                int N, int K) {
    __shared__ unsigned uA[32 * AS];
    __shared__ unsigned uB[32 * BS];
    int tid = threadIdx.x, lane = tid & 31, w = tid >> 5;
    int wr = w & 3, wc = w >> 2;
    int n0 = blockIdx.x * 64;
    int g = lane >> 2, t = lane & 3;

    float acc[2][4][4] = {};
    for (int k0 = 0; k0 < K; k0 += 32) {
#pragma unroll
        for (int it = 0; it < 4; ++it) {
            int i = tid + it * 256;
            int row = i >> 3, c = i & 7;
            int kk0 = c * 4;
            float4 v = *(const float4*)(A + (size_t)row * K + k0 + kk0);
            int mt = row >> 4, rr = row & 15, gg = rr & 7, hi = rr >> 3;
            int ks = kk0 >> 3, half = (kk0 >> 2) & 1;
            unsigned* p = &uA[(mt * 4 + ks) * AS + gg * 16 + half * 2 + hi];
            p[0] = f2tf(v.x); p[4] = f2tf(v.y); p[8] = f2tf(v.z); p[12] = f2tf(v.w);
        }
#pragma unroll
        for (int it = 0; it < 2; ++it) {
            int i = tid + it * 256;
            int n = i >> 3, c = i & 7;
            int kk0 = c * 4;
            float4 v = *(const float4*)(Bm + (size_t)(n0 + n) * K + k0 + kk0);
            int nt = n >> 3, gg = n & 7;
            int ks = kk0 >> 3, half = (kk0 >> 2) & 1;
            unsigned* p = &uB[(nt * 4 + ks) * BS + gg * 8 + half];
            p[0] = f2tf(v.x); p[2] = f2tf(v.y); p[4] = f2tf(v.z); p[6] = f2tf(v.w);
        }
        __syncthreads();
#pragma unroll
        for (int ks = 0; ks < 4; ++ks) {
            unsigned a0[4], a1[4], b[4][2];
            *(uint4*)a0 = *(const uint4*)&uA[((wr * 2 + 0) * 4 + ks) * AS + lane * 4];
            *(uint4*)a1 = *(const uint4*)&uA[((wr * 2 + 1) * 4 + ks) * AS + lane * 4];
#pragma unroll
            for (int j = 0; j < 4; ++j)
                *(uint2*)b[j] = *(const uint2*)&uB[((wc * 4 + j) * 4 + ks) * BS + lane * 2];
#pragma unroll
            for (int j = 0; j < 4; ++j) { mma8(acc[0][j], a0, b[j]); mma8(acc[1][j], a1, b[j]); }
        }
        __syncthreads();
    }
#pragma unroll
    for (int mt = 0; mt < 2; ++mt)
#pragma unroll
        for (int j = 0; j < 4; ++j)
#pragma unroll
            for (int ci = 0; ci < 4; ++ci) {
                int row = wr * 32 + mt * 16 + g + (ci >> 1) * 8;
                int col = n0 + wc * 32 + j * 8 + t * 2 + (ci & 1);
                float v = acc[mt][j][ci];
                if (EPI == 2) v = tanhf(v);
                C[(size_t)row * N + col] = v;
            }
}

// ---------------- fused LSTM pointwise + q = hn @ Wq^T (+ zero ctx) ----------------
__global__ __launch_bounds__(256) void lstm_q(const float* __restrict__ cp,
                                              const float* __restrict__ Wq,
                                              float* __restrict__ out_hn,
                                              float* __restrict__ out_cn) {
    int b = blockIdx.x, tid = threadIdx.x;
    __shared__ float hns[512];
    const float* g = g_gates + (size_t)b * 2048;
#pragma unroll
    for (int h = tid; h < 512; h += 256) {
        float ig = sigmoidf(g[h]);
        float fg = sigmoidf(g[512 + h]);
        float gg = tanhf(g[1024 + h]);
        float og = sigmoidf(g[1536 + h]);
        float cn = fg * cp[(size_t)b * 512 + h] + ig * gg;
        float hn = og * tanhf(cn);
        out_cn[(size_t)b * 512 + h] = cn;
        out_hn[(size_t)b * 512 + h] = hn;
        hns[h] = hn;
        g_oin[(size_t)b * 1024 + h] = hn;          // first half of o_in
        g_oin[(size_t)b * 1024 + 512 + h] = 0.0f;  // zero ctx accumulator
    }
    __syncthreads();
#pragma unroll
    for (int n = tid; n < 512; n += 256) {
        const float4* wr = (const float4*)(Wq + (size_t)n * 512);
        float s = 0.0f;
#pragma unroll 4
        for (int i = 0; i < 128; ++i) {
            float4 v = wr[i];
            s += v.x * hns[i * 4] + v.y * hns[i * 4 + 1] + v.z * hns[i * 4 + 2] + v.w * hns[i * 4 + 3];
        }
        g_q[(size_t)b * 512 + n] = s;
    }
}

// ---------------- fused score kernel v3 (k-chunk = 64) ----------------
#define SC_A_U32 (4 * 64 * AS)
#define SC_B_U32 (16 * 8 * BS)      /* 16 nt x 8 ks per 64-k chunk */
__global__ __launch_bounds__(256) void score_kernel(const float* __restrict__ enc,
                                                    const float* __restrict__ Wm,
                                                    const float* __restrict__ Wa) {
    extern __shared__ unsigned sm[];
    unsigned* uA  = sm;
    unsigned* uB0 = uA + SC_A_U32;
    unsigned* uB1 = uB0 + SC_B_U32;
    float* qs     = (float*)(uB1 + SC_B_U32);
    float* was    = qs + 512;
    float* rowacc = was + 512;

    int tid = threadIdx.x, lane = tid & 31, w = tid >> 5;
    int wr = w & 1, wc = w >> 1;
    int r0 = blockIdx.x * 64;
    int b = r0 >> 10;
    int g = lane >> 2, t = lane & 3;

    for (int i = tid; i < 512; i += 256) {
        qs[i] = g_q[(size_t)b * 512 + i];
        was[i] = Wa[i];
    }
    if (tid < 64) rowacc[tid] = 0.0f;

    // ---- fill A once: 64 rows x 512 k ----
#pragma unroll
    for (int it = 0; it < 32; ++it) {
        int i = tid + it * 256;
        int row = i >> 7, c = i & 127;
        int kk0 = c * 4;
        float4 v = *(const float4*)(enc + (size_t)(r0 + row) * 512 + kk0);
        int mt = row >> 4, rr = row & 15, gg = rr & 7, hi = rr >> 3;
        int ks = kk0 >> 3, half = (kk0 >> 2) & 1;
        unsigned* p = &uA[(mt * 64 + ks) * AS + gg * 16 + half * 2 + hi];
        p[0] = f2tf(v.x); p[4] = f2tf(v.y); p[8] = f2tf(v.z); p[12] = f2tf(v.w);
    }
    __syncthreads();

    for (int n0c = 0; n0c < 512; n0c += 128) {
        float acc[2][4][4] = {};
        float4 vb[8];
        // prologue: load + store k-chunk 0 (64 k)
#pragma unroll
        for (int it = 0; it < 8; ++it) {
            int i = tid + it * 256;
            int n = i >> 4, c = i & 15;
            vb[it] = *(const float4*)(Wm + (size_t)(n0c + n) * 512 + c * 4);
        }
#pragma unroll
        for (int it = 0; it < 8; ++it) {
            int i = tid + it * 256;
            int n = i >> 4, c = i & 15;
            int kk0 = c * 4, nt = n >> 3, gg = n & 7;
            int ks = kk0 >> 3, half = (kk0 >> 2) & 1;
            unsigned* p = &uB0[(nt * 8 + ks) * BS + gg * 8 + half];
            p[0] = f2tf(vb[it].x); p[2] = f2tf(vb[it].y); p[4] = f2tf(vb[it].z); p[6] = f2tf(vb[it].w);
        }
        __syncthreads();

        for (int kc = 0; kc < 8; ++kc) {
            unsigned* cur = (kc & 1) ? uB1 : uB0;
            unsigned* nxt = (kc & 1) ? uB0 : uB1;
            if (kc < 7) {
#pragma unroll
                for (int it = 0; it < 8; ++it) {
                    int i = tid + it * 256;
                    int n = i >> 4, c = i & 15;
                    vb[it] = *(const float4*)(Wm + (size_t)(n0c + n) * 512 + (kc + 1) * 64 + c * 4);
                }
            }
#pragma unroll
            for (int ks = 0; ks < 8; ++ks) {
                int ksg = kc * 8 + ks;
                unsigned a0[4], a1[4], bf[4][2];
                *(uint4*)a0 = *(const uint4*)&uA[((wr * 2 + 0) * 64 + ksg) * AS + lane * 4];
                *(uint4*)a1 = *(const uint4*)&uA[((wr * 2 + 1) * 64 + ksg) * AS + lane * 4];
#pragma unroll
                for (int j = 0; j < 4; ++j)
                    *(uint2*)bf[j] = *(const uint2*)&cur[((wc * 4 + j) * 8 + ks) * BS + lane * 2];
#pragma unroll
                for (int j = 0; j < 4; ++j) { mma8(acc[0][j], a0, bf[j]); mma8(acc[1][j], a1, bf[j]); }
            }
            if (kc < 7) {
#pragma unroll
                for (int it = 0; it < 8; ++it) {
                    int i = tid + it * 256;
                    int n = i >> 4, c = i & 15;
                    int kk0 = c * 4, nt = n >> 3, gg = n & 7;
                    int ks = kk0 >> 3, half = (kk0 >> 2) & 1;
                    unsigned* p = &nxt[(nt * 8 + ks) * BS + gg * 8 + half];
                    p[0] = f2tf(vb[it].x); p[2] = f2tf(vb[it].y); p[4] = f2tf(vb[it].z); p[6] = f2tf(vb[it].w);
                }
            }
            __syncthreads();
        }

        // epilogue
        float p4[4] = {0.f, 0.f, 0.f, 0.f};
#pragma unroll
        for (int mt = 0; mt < 2; ++mt)
#pragma unroll
            for (int j = 0; j < 4; ++j)
#pragma unroll
                for (int ci = 0; ci < 4; ++ci) {
                    int n = n0c + wc * 32 + j * 8 + t * 2 + (ci & 1);
                    p4[mt * 2 + (ci >> 1)] += was[n] * fast_tanh(acc[mt][j][ci] + qs[n]);
                }
#pragma unroll
        for (int i = 0; i < 4; ++i) {
            p4[i] += __shfl_xor_sync(0xffffffffu, p4[i], 1);
            p4[i] += __shfl_xor_sync(0xffffffffu, p4[i], 2);
        }
        if (t == 0) {
#pragma unroll
            for (int i = 0; i < 4; ++i) {
                int mt = i >> 1, h = i & 1;
                atomicAdd(&rowacc[wr * 32 + mt * 16 + g + h * 8], p4[i]);
            }
        }
    }
    __syncthreads();
    if (tid < 64) g_scores[r0 + tid] = rowacc[tid];
}

// ---------------- softmax over T ----------------
__global__ __launch_bounds__(256) void softmax_t(float* __restrict__ out_w) {
    int b = blockIdx.x, tid = threadIdx.x;
    __shared__ float red[256];
    const float* s = g_scores + (size_t)b * 1024;
    float v0 = s[tid], v1 = s[tid + 256], v2 = s[tid + 512], v3 = s[tid + 768];
    float lmax = fmaxf(fmaxf(v0, v1), fmaxf(v2, v3));
    red[tid] = lmax; __syncthreads();
    for (int st = 128; st > 0; st >>= 1) {
        if (tid < st) red[tid] = fmaxf(red[tid], red[tid + st]);
        __syncthreads();
    }
    float m = red[0];
    __syncthreads();
    float e0 = expf(v0 - m), e1 = expf(v1 - m), e2 = expf(v2 - m), e3 = expf(v3 - m);
    red[tid] = e0 + e1 + e2 + e3; __syncthreads();
    for (int st = 128; st > 0; st >>= 1) {
        if (tid < st) red[tid] += red[tid + st];
        __syncthreads();
    }
    float inv = 1.0f / red[0];
    float* w = out_w + (size_t)b * 1024;
    w[tid] = e0 * inv; w[tid + 256] = e1 * inv;
    w[tid + 512] = e2 * inv; w[tid + 768] = e3 * inv;
}

// ---------------- context partial: grid (128 b, 8 t-chunks) ----------------
__global__ __launch_bounds__(256) void ctx_partial(const float* __restrict__ enc,
                                                   const float* __restrict__ wgt) {
    int b = blockIdx.x, ch = blockIdx.y, tid = threadIdx.x;
    __shared__ float w[128];
    if (tid < 128) w[tid] = wgt[(size_t)b * 1024 + ch * 128 + tid];
    __syncthreads();

    int h0 = tid * 2;
    float c0 = 0.0f, c1 = 0.0f;
    const float* eb = enc + (size_t)b * 1024 * 512 + (size_t)ch * 128 * 512;
#pragma unroll 4
    for (int t = 0; t < 128; ++t) {
        float2 e = *(const float2*)(eb + (size_t)t * 512 + h0);
        float wt = w[t];
        c0 += wt * e.x;
        c1 += wt * e.y;
    }
    atomicAdd(&g_oin[(size_t)b * 1024 + 512 + h0], c0);
    atomicAdd(&g_oin[(size_t)b * 1024 + 512 + h0 + 1], c1);
}

// ---------------- log_softmax over V ----------------
__global__ __launch_bounds__(1024) void logsm(float* __restrict__ out) {
    int b = blockIdx.x, tid = threadIdx.x;
    __shared__ float red[1024];
    float* row = out + (size_t)b * Vv;

    float lmax = -1e30f;
    for (int i = tid; i < Vv; i += 1024) lmax = fmaxf(lmax, row[i]);
    red[tid] = lmax; __syncthreads();
    for (int s = 512; s > 0; s >>= 1) {
        if (tid < s) red[tid] = fmaxf(red[tid], red[tid + s]);
        __syncthreads();
    }
    float m = red[0];
    __syncthreads();

    float lsum = 0.0f;
    for (int i = tid; i < Vv; i += 1024) lsum += expf(row[i] - m);
    red[tid] = lsum; __syncthreads();
    for (int s = 512; s > 0; s >>= 1) {
        if (tid < s) red[tid] += red[tid + s];
        __syncthreads();
    }
    float lse = m + logf(red[0]);
    __syncthreads();

    for (int i = tid; i < Vv; i += 1024) row[i] -= lse;
}

// ---------------- launch ----------------
extern "C" void kernel_launch(void* const* d_in, const int* in_sizes, int n_in,
                              void* d_out, int out_size) {
    const float* x    = (const float*)d_in[0];
    const float* hp   = (const float*)d_in[1];
    const float* cp   = (const float*)d_in[2];
    const float* op   = (const float*)d_in[3];
    const float* enc  = (const float*)d_in[4];
    const float* Wih  = (const float*)d_in[5];
    const float* Whh  = (const float*)d_in[6];
    const float* bih  = (const float*)d_in[7];
    const float* bhh  = (const float*)d_in[8];
    const float* Wq   = (const float*)d_in[9];
    const float* Wm   = (const float*)d_in[10];
    const float* Wa   = (const float*)d_in[11];
    const float* Wo   = (const float*)d_in[12];
    const float* Wout = (const float*)d_in[13];

    float* out        = (float*)d_out;
    float* out_logits = out;
    float* out_hn     = out + (size_t)Bb * Vv;
    float* out_cn     = out_hn + Bb * Hh;
    float* out_on     = out_cn + Bb * Hh;
    float* out_w      = out_on + Bb * Hh;

    float *pgates, *poin;
    cudaGetSymbolAddress((void**)&pgates, g_gates);
    cudaGetSymbolAddress((void**)&poin,  g_oin);

    size_t score_smem = (size_t)(SC_A_U32 + 2 * SC_B_U32 + 512 + 512 + 64) * 4;
    cudaFuncSetAttribute(score_kernel, cudaFuncAttributeMaxDynamicSharedMemorySize,
                         (int)score_smem);

    // 1. gates = [x|op|hp] @ [Wih|Whh]^T + bias
    gates_gemm<<<32, 256>>>(x, op, hp, Wih, Whh, bih, bhh, pgates);
    // 2. LSTM pointwise + q = hn @ Wq^T (+ zero ctx accumulator)
    lstm_q<<<128, 256>>>(cp, Wq, out_hn, out_cn);
    // 3. fused scores
    score_kernel<<<2048, 256, score_smem>>>(enc, Wm, Wa);
    // 4. softmax over T
    softmax_t<<<128, 256>>>(out_w);
    // 5. context (1024 CTAs, atomic accumulate into g_oin[:,512:])
    ctx_partial<<<dim3(128, 8), 256>>>(enc, out_w);
    // 6. on = tanh(o_in @ Wo^T)
    mma_gemm<2><<<8, 256>>>(poin, Wo, out_on, 512, 1024);
    // 7. logits = on @ Wout^T
    mma_gemm<0><<<500, 256>>>(out_on, Wout, out_logits, 32000, 512);
    // 8. log_softmax in place
    logsm<<<128, 1024>>>(out_logits);
}